// round 16
// baseline (speedup 1.0000x reference)
#include <cuda_runtime.h>
#include <cstdint>

// Problem constants: B=64, S=512, A=8, D=128, C=1024
#define PB  64
#define PS  512
#define PA  8
#define PD  128

#define LEN_BLOCKS 64   // first LEN_BLOCKS blocks compute candidate_len
#define ITER 8          // candidates per warp
#define NW   4          // warps per block
#define CPB  (NW * ITER)   // 32 candidates per gather block
#define STAGES 4        // cp.async pipeline depth

__device__ __forceinline__ void cpasync16(uint32_t dst_smem, const void* src) {
    asm volatile("cp.async.cg.shared.global [%0], [%1], 16;"
                 :: "r"(dst_smem), "l"(src));
}
__device__ __forceinline__ void cpcommit() {
    asm volatile("cp.async.commit_group;");
}
__device__ __forceinline__ void cpwait3() {
    asm volatile("cp.async.wait_group 3;");
}
__device__ __forceinline__ void cpwait0() {
    asm volatile("cp.async.wait_group 0;");
}

// ---------------------------------------------------------------------------
// blocks [0,64):  candidate_len per batch (128 thr, 8 cands/thread, MLP-8).
// blocks [64,..): gather — 4 warps x 8 candidates, cp.async depth-4 pipeline.
//   Small outputs flushed PER-WARP from registers via shuffles (coalesced,
//   no SMEM staging, no __syncthreads) -> no block-wide epilogue convoy.
//   2048 gather blocks -> ~13.8 blocks/SM -> <=7% last-wave imbalance.
// ---------------------------------------------------------------------------
__global__ void __launch_bounds__(128)
cand_kernel(const float*  __restrict__ word_repr,
            const int*    __restrict__ anchor_cls,
            const int*    __restrict__ anchor_loc,
            const int*    __restrict__ cand_idx,
            float*        __restrict__ out,
            long long off_label,
            long long off_mask,
            long long off_loc,
            long long off_len,
            long long off_scalar,   // -1 if absent
            float scalar_val,
            int BC, int C)
{
    if (blockIdx.x < LEN_BLOCKS) {
        // ---- len role: 128 threads, 8 consecutive candidates each ----
        __shared__ int rsm[4];
        int batch = blockIdx.x;
        int c8 = batch * C + threadIdx.x * 8;      // 8 consecutive candidates

        // 96B of idx data = 6 aligned independent int4 loads.
        const int4* ip = reinterpret_cast<const int4*>(cand_idx + 3 * c8);
        int4 q0 = ip[0], q1 = ip[1], q2 = ip[2], q3 = ip[3], q4 = ip[4], q5 = ip[5];

        long long f0 = (((long long)q0.x * PS + q0.y) * PA + q0.z);
        long long f1 = (((long long)q0.w * PS + q1.x) * PA + q1.y);
        long long f2 = (((long long)q1.z * PS + q1.w) * PA + q2.x);
        long long f3 = (((long long)q2.y * PS + q2.z) * PA + q2.w);
        long long f4 = (((long long)q3.x * PS + q3.y) * PA + q3.z);
        long long f5 = (((long long)q3.w * PS + q4.x) * PA + q4.y);
        long long f6 = (((long long)q4.z * PS + q4.w) * PA + q5.x);
        long long f7 = (((long long)q5.y * PS + q5.z) * PA + q5.w);

        // 8 independent loc loads (MLP=8).
        int2 l0 = *reinterpret_cast<const int2*>(anchor_loc + f0 * 2);
        int2 l1 = *reinterpret_cast<const int2*>(anchor_loc + f1 * 2);
        int2 l2 = *reinterpret_cast<const int2*>(anchor_loc + f2 * 2);
        int2 l3 = *reinterpret_cast<const int2*>(anchor_loc + f3 * 2);
        int2 l4 = *reinterpret_cast<const int2*>(anchor_loc + f4 * 2);
        int2 l5 = *reinterpret_cast<const int2*>(anchor_loc + f5 * 2);
        int2 l6 = *reinterpret_cast<const int2*>(anchor_loc + f6 * 2);
        int2 l7 = *reinterpret_cast<const int2*>(anchor_loc + f7 * 2);

        int sum = (l0.x != l0.y) + (l1.x != l1.y) + (l2.x != l2.y) + (l3.x != l3.y)
                + (l4.x != l4.y) + (l5.x != l5.y) + (l6.x != l6.y) + (l7.x != l7.y);

        #pragma unroll
        for (int o = 16; o > 0; o >>= 1)
            sum += __shfl_down_sync(0xFFFFFFFFu, sum, o);

        int lane = threadIdx.x & 31;
        int wid  = threadIdx.x >> 5;
        if (lane == 0) rsm[wid] = sum;
        __syncthreads();
        if (threadIdx.x == 0) {
            int total = rsm[0] + rsm[1] + rsm[2] + rsm[3];
            __stcs(out + off_len + batch, fmaxf((float)total, 1.0f));
            if (batch == 0 && off_scalar >= 0)
                __stcs(out + off_scalar, scalar_val);
        }
        return;
    }

    // ---- gather role ----
    __shared__ __align__(16) float s_stage[NW][STAGES][PD];  // 8 KB

    int wid  = threadIdx.x >> 5;
    int lane = threadIdx.x & 31;
    int cb   = (blockIdx.x - LEN_BLOCKS) * CPB;
    int c0   = cb + wid * ITER;

    // --- prologue: all 8 flats via one coalesced idx load + shuffles ---
    int val = 0;
    if (lane < 3 * ITER) val = cand_idx[3 * c0 + lane];

    int bb = __shfl_sync(0xFFFFFFFFu, val, (lane < 8) ? 3 * lane + 0 : 0);
    int ww = __shfl_sync(0xFFFFFFFFu, val, (lane < 8) ? 3 * lane + 1 : 0);
    int aa = __shfl_sync(0xFFFFFFFFu, val, (lane < 8) ? 3 * lane + 2 : 0);
    long long myflat = (((long long)bb * PS + ww) * PA + aa);
    int flat_lo = (int)(myflat & 0xFFFFFFFFll);
    int flat_hi = (int)(myflat >> 32);

    uint32_t stage_base = (uint32_t)__cvta_generic_to_shared(&s_stage[wid][0][0]);

    #pragma unroll
    for (int i = 0; i < STAGES; i++) {
        int lo = __shfl_sync(0xFFFFFFFFu, flat_lo, i);
        int hi = __shfl_sync(0xFFFFFFFFu, flat_hi, i);
        long long fl = ((long long)hi << 32) | (unsigned int)lo;
        const float* src = word_repr + fl * PD + lane * 4;
        cpasync16(stage_base + (uint32_t)(i * PD * 4) + lane * 16, src);
        cpcommit();
    }

    // loc/cls for my candidate (lanes 0..7), overlapping the cp.asyncs.
    float mymask = 0.0f, mylabel = 0.0f, mylocx = 0.0f, mylocy = 0.0f;
    if (lane < ITER) {
        int2 loc = *reinterpret_cast<const int2*>(anchor_loc + myflat * 2);
        int  cls = anchor_cls[myflat];
        mymask  = (loc.x != loc.y) ? 1.0f : 0.0f;
        mylabel = (float)cls;
        mylocx  = (float)loc.x;
        mylocy  = (float)loc.y;
    }

    // --- per-warp coalesced flush of small outputs (register->global) ---
    if (lane < ITER) {
        __stcs(out + off_label + c0 + lane, mylabel);
        __stcs(out + off_mask  + c0 + lane, mymask);
    }
    {
        // loc: 16 consecutive floats per warp; lane t<16 stores component
        // (t&1 ? y : x) of candidate (t>>1), fetched via shuffle.
        float lx = __shfl_sync(0xFFFFFFFFu, mylocx, (lane >> 1) & 7);
        float ly = __shfl_sync(0xFFFFFFFFu, mylocy, (lane >> 1) & 7);
        if (lane < 2 * ITER)
            __stcs(out + off_loc + 2 * (long long)c0 + lane, (lane & 1) ? ly : lx);
    }

    // --- main pipeline ---
    #pragma unroll
    for (int i = 0; i < ITER; i++) {
        cpwait3();
        int slot = i & (STAGES - 1);

        float mask = __shfl_sync(0xFFFFFFFFu, mymask, i);
        float4 t = *reinterpret_cast<float4*>(&s_stage[wid][slot][lane * 4]);
        t.x *= mask; t.y *= mask; t.z *= mask; t.w *= mask;
        __stcs(reinterpret_cast<float4*>(out + (long long)(c0 + i) * PD) + lane, t);

        if (i + STAGES < ITER) {
            int lo = __shfl_sync(0xFFFFFFFFu, flat_lo, i + STAGES);
            int hi = __shfl_sync(0xFFFFFFFFu, flat_hi, i + STAGES);
            long long fl = ((long long)hi << 32) | (unsigned int)lo;
            const float* src = word_repr + fl * PD + lane * 4;
            cpasync16(stage_base + (uint32_t)(slot * PD * 4) + lane * 16, src);
        }
        cpcommit();
    }
    cpwait0();
}

// ---------------------------------------------------------------------------
// Host launcher
// ---------------------------------------------------------------------------
extern "C" void kernel_launch(void* const* d_in, const int* in_sizes, int n_in,
                              void* d_out, int out_size)
{
    const float* word_repr  = (const float*)d_in[0];  // (B,S,A,D) fp32
    const int*   anchor_cls = (const int*)d_in[1];    // (B,S,A)   int32
    const int*   anchor_loc = (const int*)d_in[2];    // (B,S,A,2) int32
    const int*   cand_idx   = (const int*)d_in[3];    // (B*C, 3)  int32
    float* out = (float*)d_out;

    int BC = in_sizes[3] / 3;          // 65536
    int C  = BC / PB;                  // 1024

    // Output tuple layout (reference return order):
    //   repr (B*C*D) | label (B*C) | [num (1)] | len (B) | mask (B*C) | loc (B*C*2)
    long long n_repr = (long long)BC * PD;
    long long total_with_scalar = n_repr + BC + 1 + PB + BC + 2LL * BC;

    long long off_label = n_repr;
    long long off_scalar, off_len;
    if ((long long)out_size >= total_with_scalar) {
        off_scalar = off_label + BC;
        off_len    = off_scalar + 1;
    } else {
        off_scalar = -1;
        off_len    = off_label + BC;
    }
    long long off_mask = off_len + PB;
    long long off_loc  = off_mask + BC;

    int threads = 128;                                        // 4 warps/block
    int blocks  = LEN_BLOCKS + (BC + CPB - 1) / CPB;          // 64 + 2048
    cand_kernel<<<blocks, threads>>>(word_repr, anchor_cls, anchor_loc,
                                     cand_idx, out,
                                     off_label, off_mask, off_loc,
                                     off_len, off_scalar,
                                     (float)C, BC, C);
}

// round 17
// speedup vs baseline: 1.2083x; 1.2083x over previous
#include <cuda_runtime.h>
#include <cstdint>

// Problem constants: B=64, S=512, A=8, D=128, C=1024
#define PB  64
#define PS  512
#define PA  8
#define PD  128

#define LEN_BLOCKS 64   // first LEN_BLOCKS blocks compute candidate_len
#define ITER 8          // candidates per warp
#define NW   4          // warps per block
#define CPB  (NW * ITER)   // 32 candidates per gather block
#define STAGES 4        // cp.async pipeline depth

__device__ __forceinline__ void cpasync16(uint32_t dst_smem, const void* src) {
    asm volatile("cp.async.cg.shared.global [%0], [%1], 16;"
                 :: "r"(dst_smem), "l"(src));
}
__device__ __forceinline__ void cpcommit() {
    asm volatile("cp.async.commit_group;");
}
__device__ __forceinline__ void cpwait3() {
    asm volatile("cp.async.wait_group 3;");
}
__device__ __forceinline__ void cpwait0() {
    asm volatile("cp.async.wait_group 0;");
}

// ---------------------------------------------------------------------------
// blocks [0,64):  candidate_len per batch (128 thr, 8 cands/thread, MLP-8).
// blocks [64,..): gather — 4 warps x 8 candidates, cp.async depth-4 pipeline.
//   Small outputs flushed PER-WARP from registers via shuffles (coalesced,
//   no SMEM staging, no __syncthreads) -> no block-wide epilogue convoy.
//   2048 gather blocks -> ~13.8 blocks/SM -> <=7% last-wave imbalance.
// ---------------------------------------------------------------------------
__global__ void __launch_bounds__(128)
cand_kernel(const float*  __restrict__ word_repr,
            const int*    __restrict__ anchor_cls,
            const int*    __restrict__ anchor_loc,
            const int*    __restrict__ cand_idx,
            float*        __restrict__ out,
            long long off_label,
            long long off_mask,
            long long off_loc,
            long long off_len,
            long long off_scalar,   // -1 if absent
            float scalar_val,
            int BC, int C)
{
    if (blockIdx.x < LEN_BLOCKS) {
        // ---- len role: 128 threads, 8 consecutive candidates each ----
        __shared__ int rsm[4];
        int batch = blockIdx.x;
        int c8 = batch * C + threadIdx.x * 8;      // 8 consecutive candidates

        // 96B of idx data = 6 aligned independent int4 loads.
        const int4* ip = reinterpret_cast<const int4*>(cand_idx + 3 * c8);
        int4 q0 = ip[0], q1 = ip[1], q2 = ip[2], q3 = ip[3], q4 = ip[4], q5 = ip[5];

        long long f0 = (((long long)q0.x * PS + q0.y) * PA + q0.z);
        long long f1 = (((long long)q0.w * PS + q1.x) * PA + q1.y);
        long long f2 = (((long long)q1.z * PS + q1.w) * PA + q2.x);
        long long f3 = (((long long)q2.y * PS + q2.z) * PA + q2.w);
        long long f4 = (((long long)q3.x * PS + q3.y) * PA + q3.z);
        long long f5 = (((long long)q3.w * PS + q4.x) * PA + q4.y);
        long long f6 = (((long long)q4.z * PS + q4.w) * PA + q5.x);
        long long f7 = (((long long)q5.y * PS + q5.z) * PA + q5.w);

        // 8 independent loc loads (MLP=8).
        int2 l0 = *reinterpret_cast<const int2*>(anchor_loc + f0 * 2);
        int2 l1 = *reinterpret_cast<const int2*>(anchor_loc + f1 * 2);
        int2 l2 = *reinterpret_cast<const int2*>(anchor_loc + f2 * 2);
        int2 l3 = *reinterpret_cast<const int2*>(anchor_loc + f3 * 2);
        int2 l4 = *reinterpret_cast<const int2*>(anchor_loc + f4 * 2);
        int2 l5 = *reinterpret_cast<const int2*>(anchor_loc + f5 * 2);
        int2 l6 = *reinterpret_cast<const int2*>(anchor_loc + f6 * 2);
        int2 l7 = *reinterpret_cast<const int2*>(anchor_loc + f7 * 2);

        int sum = (l0.x != l0.y) + (l1.x != l1.y) + (l2.x != l2.y) + (l3.x != l3.y)
                + (l4.x != l4.y) + (l5.x != l5.y) + (l6.x != l6.y) + (l7.x != l7.y);

        #pragma unroll
        for (int o = 16; o > 0; o >>= 1)
            sum += __shfl_down_sync(0xFFFFFFFFu, sum, o);

        int lane = threadIdx.x & 31;
        int wid  = threadIdx.x >> 5;
        if (lane == 0) rsm[wid] = sum;
        __syncthreads();
        if (threadIdx.x == 0) {
            int total = rsm[0] + rsm[1] + rsm[2] + rsm[3];
            __stcs(out + off_len + batch, fmaxf((float)total, 1.0f));
            if (batch == 0 && off_scalar >= 0)
                __stcs(out + off_scalar, scalar_val);
        }
        return;
    }

    // ---- gather role ----
    __shared__ __align__(16) float s_stage[NW][STAGES][PD];  // 8 KB

    int wid  = threadIdx.x >> 5;
    int lane = threadIdx.x & 31;
    int cb   = (blockIdx.x - LEN_BLOCKS) * CPB;
    int c0   = cb + wid * ITER;

    // --- prologue: all 8 flats via one coalesced idx load + shuffles ---
    int val = 0;
    if (lane < 3 * ITER) val = cand_idx[3 * c0 + lane];

    int bb = __shfl_sync(0xFFFFFFFFu, val, (lane < 8) ? 3 * lane + 0 : 0);
    int ww = __shfl_sync(0xFFFFFFFFu, val, (lane < 8) ? 3 * lane + 1 : 0);
    int aa = __shfl_sync(0xFFFFFFFFu, val, (lane < 8) ? 3 * lane + 2 : 0);
    long long myflat = (((long long)bb * PS + ww) * PA + aa);
    int flat_lo = (int)(myflat & 0xFFFFFFFFll);
    int flat_hi = (int)(myflat >> 32);

    uint32_t stage_base = (uint32_t)__cvta_generic_to_shared(&s_stage[wid][0][0]);

    #pragma unroll
    for (int i = 0; i < STAGES; i++) {
        int lo = __shfl_sync(0xFFFFFFFFu, flat_lo, i);
        int hi = __shfl_sync(0xFFFFFFFFu, flat_hi, i);
        long long fl = ((long long)hi << 32) | (unsigned int)lo;
        const float* src = word_repr + fl * PD + lane * 4;
        cpasync16(stage_base + (uint32_t)(i * PD * 4) + lane * 16, src);
        cpcommit();
    }

    // loc/cls for my candidate (lanes 0..7), overlapping the cp.asyncs.
    float mymask = 0.0f, mylabel = 0.0f, mylocx = 0.0f, mylocy = 0.0f;
    if (lane < ITER) {
        int2 loc = *reinterpret_cast<const int2*>(anchor_loc + myflat * 2);
        int  cls = anchor_cls[myflat];
        mymask  = (loc.x != loc.y) ? 1.0f : 0.0f;
        mylabel = (float)cls;
        mylocx  = (float)loc.x;
        mylocy  = (float)loc.y;
    }

    // --- per-warp coalesced flush of small outputs (register->global) ---
    if (lane < ITER) {
        __stcs(out + off_label + c0 + lane, mylabel);
        __stcs(out + off_mask  + c0 + lane, mymask);
    }
    {
        // loc: 16 consecutive floats per warp; lane t<16 stores component
        // (t&1 ? y : x) of candidate (t>>1), fetched via shuffle.
        float lx = __shfl_sync(0xFFFFFFFFu, mylocx, (lane >> 1) & 7);
        float ly = __shfl_sync(0xFFFFFFFFu, mylocy, (lane >> 1) & 7);
        if (lane < 2 * ITER)
            __stcs(out + off_loc + 2 * (long long)c0 + lane, (lane & 1) ? ly : lx);
    }

    // --- main pipeline ---
    #pragma unroll
    for (int i = 0; i < ITER; i++) {
        cpwait3();
        int slot = i & (STAGES - 1);

        float mask = __shfl_sync(0xFFFFFFFFu, mymask, i);
        float4 t = *reinterpret_cast<float4*>(&s_stage[wid][slot][lane * 4]);
        t.x *= mask; t.y *= mask; t.z *= mask; t.w *= mask;
        __stcs(reinterpret_cast<float4*>(out + (long long)(c0 + i) * PD) + lane, t);

        if (i + STAGES < ITER) {
            int lo = __shfl_sync(0xFFFFFFFFu, flat_lo, i + STAGES);
            int hi = __shfl_sync(0xFFFFFFFFu, flat_hi, i + STAGES);
            long long fl = ((long long)hi << 32) | (unsigned int)lo;
            const float* src = word_repr + fl * PD + lane * 4;
            cpasync16(stage_base + (uint32_t)(slot * PD * 4) + lane * 16, src);
        }
        cpcommit();
    }
    cpwait0();
}

// ---------------------------------------------------------------------------
// Host launcher
// ---------------------------------------------------------------------------
extern "C" void kernel_launch(void* const* d_in, const int* in_sizes, int n_in,
                              void* d_out, int out_size)
{
    const float* word_repr  = (const float*)d_in[0];  // (B,S,A,D) fp32
    const int*   anchor_cls = (const int*)d_in[1];    // (B,S,A)   int32
    const int*   anchor_loc = (const int*)d_in[2];    // (B,S,A,2) int32
    const int*   cand_idx   = (const int*)d_in[3];    // (B*C, 3)  int32
    float* out = (float*)d_out;

    int BC = in_sizes[3] / 3;          // 65536
    int C  = BC / PB;                  // 1024

    // Output tuple layout (reference return order):
    //   repr (B*C*D) | label (B*C) | [num (1)] | len (B) | mask (B*C) | loc (B*C*2)
    long long n_repr = (long long)BC * PD;
    long long total_with_scalar = n_repr + BC + 1 + PB + BC + 2LL * BC;

    long long off_label = n_repr;
    long long off_scalar, off_len;
    if ((long long)out_size >= total_with_scalar) {
        off_scalar = off_label + BC;
        off_len    = off_scalar + 1;
    } else {
        off_scalar = -1;
        off_len    = off_label + BC;
    }
    long long off_mask = off_len + PB;
    long long off_loc  = off_mask + BC;

    int threads = 128;                                        // 4 warps/block
    int blocks  = LEN_BLOCKS + (BC + CPB - 1) / CPB;          // 64 + 2048
    cand_kernel<<<blocks, threads>>>(word_repr, anchor_cls, anchor_loc,
                                     cand_idx, out,
                                     off_label, off_mask, off_loc,
                                     off_len, off_scalar,
                                     (float)C, BC, C);
}